// round 16
// baseline (speedup 1.0000x reference)
#include <cuda_runtime.h>
#include <math.h>
#include <stdint.h>

// Problem constants
#define BB 4
#define NN 32768
#define KK 16
#define IN_DIM 32
#define HID 64
#define OUT_DIM 32
#define KIN 36
#define KH 64

typedef unsigned long long ull;
typedef unsigned int uint;

// Scratch: pointwise-MLP output x (B,N,32) = 16 MB (fp32; quantized at staging)
__device__ float g_x[BB * NN * OUT_DIM];

// bf16 B-fragment image, PAIR layout: n-tile pair per 128-word block;
// word = pb*128 + lane*4 + r, r = {b0,b1 of nt=2pn, b0,b1 of nt=2pn+1}.
// k16 tiles: W1 KT=3 (pad 36->48), W2 KT=4, W3 KT=4.  Total 18 KB.
#define W1F_OFF 0
#define W1F_SIZE (3 * 4 * 128)    // 1536 words
#define W2F_OFF (W1F_OFF + W1F_SIZE)
#define W2F_SIZE (4 * 4 * 128)    // 2048
#define W3F_OFF (W2F_OFF + W2F_SIZE)
#define W3F_SIZE (4 * 2 * 128)    // 1024
#define WF_TOTAL (W3F_OFF + W3F_SIZE)  // 4608 words = 18 KB
__device__ float g_wfrag[WF_TOTAL];

// Small params in constant bank
__constant__ float cbk1[KH];
__constant__ float cbk2[KH];
__constant__ float cbk3[OUT_DIM];
__constant__ float cG[OUT_DIM];
__constant__ float cBt[OUT_DIM];
__constant__ ulonglong2 cWp1[IN_DIM * HID / 4];
__constant__ ulonglong2 cWp2[HID * OUT_DIM / 4];
__constant__ float cbp1[HID];
__constant__ float cbp2[OUT_DIM];

// ---------------- helpers ----------------
__device__ __forceinline__ ull ffma2(ull a, ull b, ull c) {
    ull d;
    asm("fma.rn.f32x2 %0, %1, %2, %3;" : "=l"(d) : "l"(a), "l"(b), "l"(c));
    return d;
}
__device__ __forceinline__ ull pack2(float lo, float hi) {
    ull d;
    asm("mov.b64 %0, {%1, %2};" : "=l"(d) : "r"(__float_as_uint(lo)), "r"(__float_as_uint(hi)));
    return d;
}
__device__ __forceinline__ ull pack_dup(float v) {
    ull d;
    asm("mov.b64 %0, {%1, %1};" : "=l"(d) : "r"(__float_as_uint(v)));
    return d;
}
__device__ __forceinline__ void unpack2(ull p, float& lo, float& hi) {
    uint a, b;
    asm("mov.b64 {%0, %1}, %2;" : "=r"(a), "=r"(b) : "l"(p));
    lo = __uint_as_float(a); hi = __uint_as_float(b);
}
// pack two f32 -> bf16x2 word, lo in low half
__device__ __forceinline__ uint bf2(float lo, float hi) {
    uint d;
    asm("cvt.rn.bf16x2.f32 %0, %1, %2;" : "=r"(d) : "f"(hi), "f"(lo));
    return d;
}
// Branchless gelu: A&S 7.1.26 erf (|eps| <= 1.5e-7)
__device__ __forceinline__ float gelu_fast(float x) {
    float z  = 0.7071067811865476f * x;
    float az = fabsf(z);
    float d  = fmaf(0.3275911f, az, 1.0f);
    float t;
    asm("rcp.approx.f32 %0, %1;" : "=f"(t) : "f"(d));
    float p  = fmaf(1.061405429f, t, -1.453152027f);
    p = fmaf(p, t, 1.421413741f);
    p = fmaf(p, t, -0.284496736f);
    p = fmaf(p, t, 0.254829592f);
    p = p * t;
    float e  = __expf(-az * az);
    float er = fmaf(-p, e, 1.0f);
    er = copysignf(er, z);
    float hx = 0.5f * x;
    return fmaf(hx, er, hx);
}
__device__ __forceinline__ void mma_bf16(
    float& c0, float& c1, float& c2, float& c3,
    uint a0, uint a1, uint a2, uint a3, uint b0, uint b1)
{
    asm("mma.sync.aligned.m16n8k16.row.col.f32.bf16.bf16.f32 "
        "{%0,%1,%2,%3}, {%4,%5,%6,%7}, {%8,%9}, {%0,%1,%2,%3};"
        : "+f"(c0), "+f"(c1), "+f"(c2), "+f"(c3)
        : "r"(a0), "r"(a1), "r"(a2), "r"(a3), "r"(b0), "r"(b1));
}

// ---------------------------------------------------------------------------
// Kernel 0: pack weights into PAIRED bf16 B-fragment order (m16n8k16).
// ---------------------------------------------------------------------------
__device__ __forceinline__ void pack_layer_bf16(
    float* dst, const float* W, int Kdim, int Ncols, int KT, int NT,
    int nwords, int tid, int stride)
{
    for (int i = tid; i < nwords; i += stride) {
        int pb = i >> 7;
        int lane = (i & 127) >> 2;
        int r = i & 3;
        int ntp = r >> 1, reg = r & 1;
        int kt = pb / (NT / 2);
        int pn = pb % (NT / 2);
        int nt = 2 * pn + ntp;
        int gid = lane >> 2, t0 = lane & 3;
        int k0 = kt * 16 + 2 * t0 + reg * 8;
        int n = nt * 8 + gid;
        float lo = (k0 < Kdim) ? W[k0 * Ncols + n] : 0.0f;
        float hi = (k0 + 1 < Kdim) ? W[(k0 + 1) * Ncols + n] : 0.0f;
        dst[i] = __uint_as_float(bf2(lo, hi));
    }
}

__global__ void pack_weights(const float* __restrict__ Wk1,
                             const float* __restrict__ Wk2,
                             const float* __restrict__ Wk3)
{
    int tid = blockIdx.x * 256 + threadIdx.x;
    int stride = gridDim.x * 256;
    pack_layer_bf16(g_wfrag + W1F_OFF, Wk1, KIN, KH, 3, 8, W1F_SIZE, tid, stride);
    pack_layer_bf16(g_wfrag + W2F_OFF, Wk2, KH, KH, 4, 8, W2F_SIZE, tid, stride);
    pack_layer_bf16(g_wfrag + W3F_OFF, Wk3, KH, OUT_DIM, 4, 4, W3F_SIZE, tid, stride);
}

// ---------------------------------------------------------------------------
// Kernel 1: pointwise MLP (FFMA2, const weights)
// ---------------------------------------------------------------------------
__global__ __launch_bounds__(256) void pointwise_kernel(
    const float* __restrict__ inp)
{
    int t = blockIdx.x * 256 + threadIdx.x;
    const float4* ir = (const float4*)(inp + t * IN_DIM);

    float in[IN_DIM];
#pragma unroll
    for (int i = 0; i < IN_DIM / 4; ++i) {
        float4 v = ir[i];
        in[4*i+0] = v.x; in[4*i+1] = v.y; in[4*i+2] = v.z; in[4*i+3] = v.w;
    }

    ull acc[HID/2];
#pragma unroll
    for (int i = 0; i < HID/2; ++i) acc[i] = pack2(cbp1[2*i], cbp1[2*i+1]);
#pragma unroll
    for (int c = 0; c < IN_DIM; ++c) {
        ull v = pack_dup(in[c]);
#pragma unroll
        for (int o2 = 0; o2 < HID/4; ++o2) {
            ulonglong2 w = cWp1[c * (HID/4) + o2];
            acc[2*o2+0] = ffma2(v, w.x, acc[2*o2+0]);
            acc[2*o2+1] = ffma2(v, w.y, acc[2*o2+1]);
        }
    }
    float h[HID];
#pragma unroll
    for (int i = 0; i < HID/2; ++i) {
        float a, b; unpack2(acc[i], a, b);
        h[2*i] = gelu_fast(a); h[2*i+1] = gelu_fast(b);
    }

    ull acc2[OUT_DIM/2];
#pragma unroll
    for (int i = 0; i < OUT_DIM/2; ++i) acc2[i] = pack2(cbp2[2*i], cbp2[2*i+1]);
#pragma unroll
    for (int c = 0; c < HID; ++c) {
        ull v = pack_dup(h[c]);
#pragma unroll
        for (int o2 = 0; o2 < OUT_DIM/4; ++o2) {
            ulonglong2 w = cWp2[c * (OUT_DIM/4) + o2];
            acc2[2*o2+0] = ffma2(v, w.x, acc2[2*o2+0]);
            acc2[2*o2+1] = ffma2(v, w.y, acc2[2*o2+1]);
        }
    }
    ulonglong2* xr = (ulonglong2*)(g_x + t * OUT_DIM);
#pragma unroll
    for (int o2 = 0; o2 < OUT_DIM/4; ++o2) {
        ulonglong2 r; r.x = acc2[2*o2+0]; r.y = acc2[2*o2+1];
        xr[o2] = r;
    }
}

// ---------------------------------------------------------------------------
// Kernel 2: edge MLP on bf16 tensor cores (m16n8k16), occupancy push:
// bf16 shrank the weight image to 18KB and halved per-warp weight traffic,
// decoupling occupancy from L1 residency (R11/R12 lesson). 16 CTAs/SM
// (thread cap): smem 147KB, L1D 81KB >> 18KB image. 64 warps/SM.
// ---------------------------------------------------------------------------
#define RSW 36                                   // row stride in 32-bit words
#define NPB 4                                    // nodes (warps) per block
#define EDGE_SMEM_WORDS (NPB * 16 * RSW)         // 2304
#define EDGE_SMEM_BYTES (EDGE_SMEM_WORDS * 4)    // 9216

__global__ __launch_bounds__(128, 16) void edge_kernel(
    const float* __restrict__ igrid,
    const float* __restrict__ ogrid,
    const int*   __restrict__ nidx,
    float* __restrict__ out)
{
    extern __shared__ uint smw[];
    int tid = threadIdx.x;
    int warp = tid >> 5;
    int lane = tid & 31;
    uint* wb = smw + warp * (16 * RSW);           // warp-private buffer
    const float* __restrict__ gwf = g_wfrag;

    int node = blockIdx.x * NPB + warp;
    int b = node >> 15;
    int n = node & (NN - 1);

    int gid = lane >> 2;
    int t0 = lane & 3;

    // ---- Stage agg rows (bf16): 2 lanes per row.
    {
        int r = lane >> 1, half = lane & 1;
        int nb = nidx[n * KK + r];
        const float4* xrow = (const float4*)(g_x + (b * NN + nb) * OUT_DIM);
        uint* rowp = wb + r * RSW;
        if (half == 0) {
            uint2 p;
            p.x = bf2(igrid[nb * 2 + 0], igrid[nb * 2 + 1]);
            p.y = bf2(ogrid[n * 2 + 0], ogrid[n * 2 + 1]);
            *(uint2*)(rowp) = p;
#pragma unroll
            for (int j = 0; j < 4; ++j) {         // x[0..15] -> words 2..9
                float4 v = xrow[j];
                uint2 q; q.x = bf2(v.x, v.y); q.y = bf2(v.z, v.w);
                *(uint2*)(rowp + 2 + 2*j) = q;
            }
        } else {
#pragma unroll
            for (int j = 4; j < 8; ++j) {         // x[16..31] -> words 10..17
                float4 v = xrow[j];
                uint2 q; q.x = bf2(v.x, v.y); q.y = bf2(v.z, v.w);
                *(uint2*)(rowp + 2 + 2*j) = q;
            }
            uint2 z; z.x = 0; z.y = 0;            // pad words 18..23
            *(uint2*)(rowp + 18) = z;
            *(uint2*)(rowp + 20) = z;
            *(uint2*)(rowp + 22) = z;
        }
    }
    __syncwarp();

    float c[8][4];

    // ---- GEMM1: (16x48) @ W1(48x64) + bk1 (3 k16 tiles)
#pragma unroll
    for (int nt = 0; nt < 8; ++nt) {
        float b0 = cbk1[nt * 8 + 2 * t0], b1 = cbk1[nt * 8 + 2 * t0 + 1];
        c[nt][0] = b0; c[nt][1] = b1; c[nt][2] = b0; c[nt][3] = b1;
    }
#pragma unroll
    for (int kt = 0; kt < 3; ++kt) {
        const uint* ap = wb + gid * RSW + kt * 8 + t0;
        uint a0 = ap[0], a2 = ap[4];
        uint a1 = ap[8 * RSW], a3 = ap[8 * RSW + 4];
#pragma unroll
        for (int pn = 0; pn < 4; ++pn) {
            uint4 bb = *(const uint4*)(gwf + W1F_OFF + (kt * 4 + pn) * 128 + lane * 4);
            mma_bf16(c[2*pn][0], c[2*pn][1], c[2*pn][2], c[2*pn][3],
                     a0, a1, a2, a3, bb.x, bb.y);
            mma_bf16(c[2*pn+1][0], c[2*pn+1][1], c[2*pn+1][2], c[2*pn+1][3],
                     a0, a1, a2, a3, bb.z, bb.w);
        }
    }

    // ---- boundary 1: gelu -> bf16x2 -> work buffer (h1: 16 x 64)
    __syncwarp();
#pragma unroll
    for (int nt = 0; nt < 8; ++nt) {
        uint lo = bf2(gelu_fast(c[nt][0]), gelu_fast(c[nt][1]));
        uint hi = bf2(gelu_fast(c[nt][2]), gelu_fast(c[nt][3]));
        uint* p = wb + gid * RSW + nt * 4 + t0;
        p[0] = lo;
        p[8 * RSW] = hi;
    }
    __syncwarp();

    // ---- GEMM2: (16x64) @ W2(64x64) + bk2 (4 k16 tiles)
#pragma unroll
    for (int nt = 0; nt < 8; ++nt) {
        float b0 = cbk2[nt * 8 + 2 * t0], b1 = cbk2[nt * 8 + 2 * t0 + 1];
        c[nt][0] = b0; c[nt][1] = b1; c[nt][2] = b0; c[nt][3] = b1;
    }
#pragma unroll
    for (int kt = 0; kt < 4; ++kt) {
        const uint* ap = wb + gid * RSW + kt * 8 + t0;
        uint a0 = ap[0], a2 = ap[4];
        uint a1 = ap[8 * RSW], a3 = ap[8 * RSW + 4];
#pragma unroll
        for (int pn = 0; pn < 4; ++pn) {
            uint4 bb = *(const uint4*)(gwf + W2F_OFF + (kt * 4 + pn) * 128 + lane * 4);
            mma_bf16(c[2*pn][0], c[2*pn][1], c[2*pn][2], c[2*pn][3],
                     a0, a1, a2, a3, bb.x, bb.y);
            mma_bf16(c[2*pn+1][0], c[2*pn+1][1], c[2*pn+1][2], c[2*pn+1][3],
                     a0, a1, a2, a3, bb.z, bb.w);
        }
    }

    // ---- boundary 2: gelu -> bf16x2 -> work buffer (h2: 16 x 64)
    __syncwarp();
#pragma unroll
    for (int nt = 0; nt < 8; ++nt) {
        uint lo = bf2(gelu_fast(c[nt][0]), gelu_fast(c[nt][1]));
        uint hi = bf2(gelu_fast(c[nt][2]), gelu_fast(c[nt][3]));
        uint* p = wb + gid * RSW + nt * 4 + t0;
        p[0] = lo;
        p[8 * RSW] = hi;
    }
    __syncwarp();

    // ---- GEMM3: (16x64) @ W3(64x32) + bk3 (4 k16 tiles, 4 n-tiles)
    float c3[4][4];
#pragma unroll
    for (int nt = 0; nt < 4; ++nt) {
        float b0 = cbk3[nt * 8 + 2 * t0], b1 = cbk3[nt * 8 + 2 * t0 + 1];
        c3[nt][0] = b0; c3[nt][1] = b1; c3[nt][2] = b0; c3[nt][3] = b1;
    }
#pragma unroll
    for (int kt = 0; kt < 4; ++kt) {
        const uint* ap = wb + gid * RSW + kt * 8 + t0;
        uint a0 = ap[0], a2 = ap[4];
        uint a1 = ap[8 * RSW], a3 = ap[8 * RSW + 4];
#pragma unroll
        for (int pn = 0; pn < 2; ++pn) {
            uint4 bb = *(const uint4*)(gwf + W3F_OFF + (kt * 2 + pn) * 128 + lane * 4);
            mma_bf16(c3[2*pn][0], c3[2*pn][1], c3[2*pn][2], c3[2*pn][3],
                     a0, a1, a2, a3, bb.x, bb.y);
            mma_bf16(c3[2*pn+1][0], c3[2*pn+1][1], c3[2*pn+1][2], c3[2*pn+1][3],
                     a0, a1, a2, a3, bb.z, bb.w);
        }
    }

    // ---- Mean over K = sum over 16 rows of the 16x32 tile
    float s[8];
#pragma unroll
    for (int nt = 0; nt < 4; ++nt) {
        s[2*nt + 0] = c3[nt][0] + c3[nt][2];
        s[2*nt + 1] = c3[nt][1] + c3[nt][3];
    }
#pragma unroll
    for (int off = 4; off <= 16; off <<= 1) {
#pragma unroll
        for (int i = 0; i < 8; ++i)
            s[i] += __shfl_xor_sync(0xffffffffu, s[i], off);
    }

    // ---- residual + LayerNorm epilogue (valid work in gid==0 lanes)
    float o[8];
    if (gid == 0) {
#pragma unroll
        for (int nt = 0; nt < 4; ++nt) {
            float2 xv = *(const float2*)(g_x + node * OUT_DIM + nt * 8 + 2 * t0);
            o[2*nt + 0] = fmaf(s[2*nt + 0], 0.0625f, xv.x);
            o[2*nt + 1] = fmaf(s[2*nt + 1], 0.0625f, xv.y);
        }
    } else {
#pragma unroll
        for (int i = 0; i < 8; ++i) o[i] = 0.0f;
    }
    float part = 0.0f;
#pragma unroll
    for (int i = 0; i < 8; ++i) part += o[i];
    part += __shfl_xor_sync(0xffffffffu, part, 1);
    part += __shfl_xor_sync(0xffffffffu, part, 2);
    float mu = part * (1.0f / OUT_DIM);
    float vp = 0.0f;
#pragma unroll
    for (int i = 0; i < 8; ++i) { float d = o[i] - mu; vp = fmaf(d, d, vp); }
    vp += __shfl_xor_sync(0xffffffffu, vp, 1);
    vp += __shfl_xor_sync(0xffffffffu, vp, 2);
    if (gid == 0) {
        float rs = rsqrtf(vp * (1.0f / OUT_DIM) + 1e-5f);
#pragma unroll
        for (int nt = 0; nt < 4; ++nt) {
            int col = nt * 8 + 2 * t0;
            float2 y;
            y.x = fmaf((o[2*nt + 0] - mu) * rs, cG[col + 0], cBt[col + 0]);
            y.y = fmaf((o[2*nt + 1] - mu) * rs, cG[col + 1], cBt[col + 1]);
            *(float2*)(out + node * OUT_DIM + col) = y;
        }
    }
}

// ---------------------------------------------------------------------------
extern "C" void kernel_launch(void* const* d_in, const int* in_sizes, int n_in,
                              void* d_out, int out_size) {
    const float* inp   = (const float*)d_in[0];
    const float* igrid = (const float*)d_in[1];
    const float* ogrid = (const float*)d_in[2];
    const int*   nidx  = (const int*)  d_in[3];
    const float* Wp1   = (const float*)d_in[4];
    const float* bp1   = (const float*)d_in[5];
    const float* Wp2   = (const float*)d_in[6];
    const float* bp2   = (const float*)d_in[7];
    const float* Wk1   = (const float*)d_in[8];
    const float* bk1   = (const float*)d_in[9];
    const float* Wk2   = (const float*)d_in[10];
    const float* bk2   = (const float*)d_in[11];
    const float* Wk3   = (const float*)d_in[12];
    const float* bk3   = (const float*)d_in[13];
    const float* ln_g  = (const float*)d_in[14];
    const float* ln_b  = (const float*)d_in[15];
    float* out = (float*)d_out;

    cudaMemcpyToSymbolAsync(cbk1, bk1, KH * sizeof(float), 0, cudaMemcpyDeviceToDevice);
    cudaMemcpyToSymbolAsync(cbk2, bk2, KH * sizeof(float), 0, cudaMemcpyDeviceToDevice);
    cudaMemcpyToSymbolAsync(cbk3, bk3, OUT_DIM * sizeof(float), 0, cudaMemcpyDeviceToDevice);
    cudaMemcpyToSymbolAsync(cG,   ln_g, OUT_DIM * sizeof(float), 0, cudaMemcpyDeviceToDevice);
    cudaMemcpyToSymbolAsync(cBt,  ln_b, OUT_DIM * sizeof(float), 0, cudaMemcpyDeviceToDevice);
    cudaMemcpyToSymbolAsync(cWp1, Wp1, IN_DIM * HID * sizeof(float), 0, cudaMemcpyDeviceToDevice);
    cudaMemcpyToSymbolAsync(cWp2, Wp2, HID * OUT_DIM * sizeof(float), 0, cudaMemcpyDeviceToDevice);
    cudaMemcpyToSymbolAsync(cbp1, bp1, HID * sizeof(float), 0, cudaMemcpyDeviceToDevice);
    cudaMemcpyToSymbolAsync(cbp2, bp2, OUT_DIM * sizeof(float), 0, cudaMemcpyDeviceToDevice);

    pack_weights<<<32, 256>>>(Wk1, Wk2, Wk3);
    pointwise_kernel<<<(BB * NN) / 256, 256>>>(inp);
    edge_kernel<<<(BB * NN) / NPB, 128, EDGE_SMEM_BYTES>>>(igrid, ogrid, nidx, out);
}

// round 17
// speedup vs baseline: 2.2245x; 2.2245x over previous
#include <cuda_runtime.h>
#include <math.h>
#include <stdint.h>

// Problem constants
#define BB 4
#define NN 32768
#define KK 16
#define IN_DIM 32
#define HID 64
#define OUT_DIM 32
#define KIN 36
#define KH 64

typedef unsigned long long ull;
typedef unsigned int uint;

// Scratch: pointwise-MLP output x (B,N,32) = 16 MB (fp32; quantized at staging)
__device__ float g_x[BB * NN * OUT_DIM];

// bf16 B-fragment image, PAIR layout: n-tile pair per 128-word block;
// word = pb*128 + lane*4 + r, r = {b0,b1 of nt=2pn, b0,b1 of nt=2pn+1}.
// k16 tiles: W1 KT=3 (pad 36->48), W2 KT=4, W3 KT=4.  Total 18 KB.
#define W1F_OFF 0
#define W1F_SIZE (3 * 4 * 128)    // 1536 words
#define W2F_OFF (W1F_OFF + W1F_SIZE)
#define W2F_SIZE (4 * 4 * 128)    // 2048
#define W3F_OFF (W2F_OFF + W2F_SIZE)
#define W3F_SIZE (4 * 2 * 128)    // 1024
#define WF_TOTAL (W3F_OFF + W3F_SIZE)  // 4608 words = 18 KB
__device__ float g_wfrag[WF_TOTAL];

// Small params in constant bank
__constant__ float cbk1[KH];
__constant__ float cbk2[KH];
__constant__ float cbk3[OUT_DIM];
__constant__ float cG[OUT_DIM];
__constant__ float cBt[OUT_DIM];
__constant__ ulonglong2 cWp1[IN_DIM * HID / 4];
__constant__ ulonglong2 cWp2[HID * OUT_DIM / 4];
__constant__ float cbp1[HID];
__constant__ float cbp2[OUT_DIM];

// ---------------- helpers ----------------
__device__ __forceinline__ ull ffma2(ull a, ull b, ull c) {
    ull d;
    asm("fma.rn.f32x2 %0, %1, %2, %3;" : "=l"(d) : "l"(a), "l"(b), "l"(c));
    return d;
}
__device__ __forceinline__ ull pack2(float lo, float hi) {
    ull d;
    asm("mov.b64 %0, {%1, %2};" : "=l"(d) : "r"(__float_as_uint(lo)), "r"(__float_as_uint(hi)));
    return d;
}
__device__ __forceinline__ ull pack_dup(float v) {
    ull d;
    asm("mov.b64 %0, {%1, %1};" : "=l"(d) : "r"(__float_as_uint(v)));
    return d;
}
__device__ __forceinline__ void unpack2(ull p, float& lo, float& hi) {
    uint a, b;
    asm("mov.b64 {%0, %1}, %2;" : "=r"(a), "=r"(b) : "l"(p));
    lo = __uint_as_float(a); hi = __uint_as_float(b);
}
// pack two f32 -> bf16x2 word, lo in low half
__device__ __forceinline__ uint bf2(float lo, float hi) {
    uint d;
    asm("cvt.rn.bf16x2.f32 %0, %1, %2;" : "=r"(d) : "f"(hi), "f"(lo));
    return d;
}
// Branchless gelu: A&S 7.1.26 erf (|eps| <= 1.5e-7)
__device__ __forceinline__ float gelu_fast(float x) {
    float z  = 0.7071067811865476f * x;
    float az = fabsf(z);
    float d  = fmaf(0.3275911f, az, 1.0f);
    float t;
    asm("rcp.approx.f32 %0, %1;" : "=f"(t) : "f"(d));
    float p  = fmaf(1.061405429f, t, -1.453152027f);
    p = fmaf(p, t, 1.421413741f);
    p = fmaf(p, t, -0.284496736f);
    p = fmaf(p, t, 0.254829592f);
    p = p * t;
    float e  = __expf(-az * az);
    float er = fmaf(-p, e, 1.0f);
    er = copysignf(er, z);
    float hx = 0.5f * x;
    return fmaf(hx, er, hx);
}
__device__ __forceinline__ void mma_bf16(
    float& c0, float& c1, float& c2, float& c3,
    uint a0, uint a1, uint a2, uint a3, uint b0, uint b1)
{
    asm("mma.sync.aligned.m16n8k16.row.col.f32.bf16.bf16.f32 "
        "{%0,%1,%2,%3}, {%4,%5,%6,%7}, {%8,%9}, {%0,%1,%2,%3};"
        : "+f"(c0), "+f"(c1), "+f"(c2), "+f"(c3)
        : "r"(a0), "r"(a1), "r"(a2), "r"(a3), "r"(b0), "r"(b1));
}

// ---------------------------------------------------------------------------
// Kernel 0: pack weights into PAIRED bf16 B-fragment order (m16n8k16).
// ---------------------------------------------------------------------------
__device__ __forceinline__ void pack_layer_bf16(
    float* dst, const float* W, int Kdim, int Ncols, int KT, int NT,
    int nwords, int tid, int stride)
{
    for (int i = tid; i < nwords; i += stride) {
        int pb = i >> 7;
        int lane = (i & 127) >> 2;
        int r = i & 3;
        int ntp = r >> 1, reg = r & 1;
        int kt = pb / (NT / 2);
        int pn = pb % (NT / 2);
        int nt = 2 * pn + ntp;
        int gid = lane >> 2, t0 = lane & 3;
        int k0 = kt * 16 + 2 * t0 + reg * 8;
        int n = nt * 8 + gid;
        float lo = (k0 < Kdim) ? W[k0 * Ncols + n] : 0.0f;
        float hi = (k0 + 1 < Kdim) ? W[(k0 + 1) * Ncols + n] : 0.0f;
        dst[i] = __uint_as_float(bf2(lo, hi));
    }
}

__global__ void pack_weights(const float* __restrict__ Wk1,
                             const float* __restrict__ Wk2,
                             const float* __restrict__ Wk3)
{
    int tid = blockIdx.x * 256 + threadIdx.x;
    int stride = gridDim.x * 256;
    pack_layer_bf16(g_wfrag + W1F_OFF, Wk1, KIN, KH, 3, 8, W1F_SIZE, tid, stride);
    pack_layer_bf16(g_wfrag + W2F_OFF, Wk2, KH, KH, 4, 8, W2F_SIZE, tid, stride);
    pack_layer_bf16(g_wfrag + W3F_OFF, Wk3, KH, OUT_DIM, 4, 4, W3F_SIZE, tid, stride);
}

// ---------------------------------------------------------------------------
// Kernel 1: pointwise MLP (FFMA2, const weights)
// ---------------------------------------------------------------------------
__global__ __launch_bounds__(256) void pointwise_kernel(
    const float* __restrict__ inp)
{
    int t = blockIdx.x * 256 + threadIdx.x;
    const float4* ir = (const float4*)(inp + t * IN_DIM);

    float in[IN_DIM];
#pragma unroll
    for (int i = 0; i < IN_DIM / 4; ++i) {
        float4 v = ir[i];
        in[4*i+0] = v.x; in[4*i+1] = v.y; in[4*i+2] = v.z; in[4*i+3] = v.w;
    }

    ull acc[HID/2];
#pragma unroll
    for (int i = 0; i < HID/2; ++i) acc[i] = pack2(cbp1[2*i], cbp1[2*i+1]);
#pragma unroll
    for (int c = 0; c < IN_DIM; ++c) {
        ull v = pack_dup(in[c]);
#pragma unroll
        for (int o2 = 0; o2 < HID/4; ++o2) {
            ulonglong2 w = cWp1[c * (HID/4) + o2];
            acc[2*o2+0] = ffma2(v, w.x, acc[2*o2+0]);
            acc[2*o2+1] = ffma2(v, w.y, acc[2*o2+1]);
        }
    }
    float h[HID];
#pragma unroll
    for (int i = 0; i < HID/2; ++i) {
        float a, b; unpack2(acc[i], a, b);
        h[2*i] = gelu_fast(a); h[2*i+1] = gelu_fast(b);
    }

    ull acc2[OUT_DIM/2];
#pragma unroll
    for (int i = 0; i < OUT_DIM/2; ++i) acc2[i] = pack2(cbp2[2*i], cbp2[2*i+1]);
#pragma unroll
    for (int c = 0; c < HID; ++c) {
        ull v = pack_dup(h[c]);
#pragma unroll
        for (int o2 = 0; o2 < OUT_DIM/4; ++o2) {
            ulonglong2 w = cWp2[c * (OUT_DIM/4) + o2];
            acc2[2*o2+0] = ffma2(v, w.x, acc2[2*o2+0]);
            acc2[2*o2+1] = ffma2(v, w.y, acc2[2*o2+1]);
        }
    }
    ulonglong2* xr = (ulonglong2*)(g_x + t * OUT_DIM);
#pragma unroll
    for (int o2 = 0; o2 < OUT_DIM/4; ++o2) {
        ulonglong2 r; r.x = acc2[2*o2+0]; r.y = acc2[2*o2+1];
        xr[o2] = r;
    }
}

// ---------------------------------------------------------------------------
// Kernel 2: edge MLP on bf16 tensor cores (m16n8k16) — REGISTER-RESIDENT
// layer boundaries. Key identity: lane (gid,t0)'s C-fragment cols of tile
// nt=2kt (+1) are exactly the A-fragment bf16 pairs (a0..a3) of k-tile kt
// for the next GEMM. Boundaries = gelu+bf16x2 pack in registers; no smem
// round-trip, no syncwarp. smem used only for initial agg staging.
// (128,8): 64 regs/thread (register-file wall, R16 lesson), 32 warps/SM.
// ---------------------------------------------------------------------------
#define RSW 36                                   // row stride in 32-bit words
#define NPB 4                                    // nodes (warps) per block
#define EDGE_SMEM_WORDS (NPB * 16 * RSW)         // 2304
#define EDGE_SMEM_BYTES (EDGE_SMEM_WORDS * 4)    // 9216

__global__ __launch_bounds__(128, 8) void edge_kernel(
    const float* __restrict__ igrid,
    const float* __restrict__ ogrid,
    const int*   __restrict__ nidx,
    float* __restrict__ out)
{
    extern __shared__ uint smw[];
    int tid = threadIdx.x;
    int warp = tid >> 5;
    int lane = tid & 31;
    uint* wb = smw + warp * (16 * RSW);           // warp-private staging buffer
    const float* __restrict__ gwf = g_wfrag;

    int node = blockIdx.x * NPB + warp;
    int b = node >> 15;
    int n = node & (NN - 1);

    int gid = lane >> 2;
    int t0 = lane & 3;

    // ---- Stage agg rows (bf16): 2 lanes per row.
    {
        int r = lane >> 1, half = lane & 1;
        int nb = nidx[n * KK + r];
        const float4* xrow = (const float4*)(g_x + (b * NN + nb) * OUT_DIM);
        uint* rowp = wb + r * RSW;
        if (half == 0) {
            uint2 p;
            p.x = bf2(igrid[nb * 2 + 0], igrid[nb * 2 + 1]);
            p.y = bf2(ogrid[n * 2 + 0], ogrid[n * 2 + 1]);
            *(uint2*)(rowp) = p;
#pragma unroll
            for (int j = 0; j < 4; ++j) {         // x[0..15] -> words 2..9
                float4 v = xrow[j];
                uint2 q; q.x = bf2(v.x, v.y); q.y = bf2(v.z, v.w);
                *(uint2*)(rowp + 2 + 2*j) = q;
            }
        } else {
#pragma unroll
            for (int j = 4; j < 8; ++j) {         // x[16..31] -> words 10..17
                float4 v = xrow[j];
                uint2 q; q.x = bf2(v.x, v.y); q.y = bf2(v.z, v.w);
                *(uint2*)(rowp + 2 + 2*j) = q;
            }
            uint2 z; z.x = 0; z.y = 0;            // pad words 18..23
            *(uint2*)(rowp + 18) = z;
            *(uint2*)(rowp + 20) = z;
            *(uint2*)(rowp + 22) = z;
        }
    }
    __syncwarp();

    float c[8][4];

    // ---- GEMM1: (16x48) @ W1(48x64) + bk1 (3 k16 tiles; A from smem)
#pragma unroll
    for (int nt = 0; nt < 8; ++nt) {
        float b0 = cbk1[nt * 8 + 2 * t0], b1 = cbk1[nt * 8 + 2 * t0 + 1];
        c[nt][0] = b0; c[nt][1] = b1; c[nt][2] = b0; c[nt][3] = b1;
    }
#pragma unroll
    for (int kt = 0; kt < 3; ++kt) {
        const uint* ap = wb + gid * RSW + kt * 8 + t0;
        uint a0 = ap[0], a2 = ap[4];
        uint a1 = ap[8 * RSW], a3 = ap[8 * RSW + 4];
#pragma unroll
        for (int pn = 0; pn < 4; ++pn) {
            uint4 bb = *(const uint4*)(gwf + W1F_OFF + (kt * 4 + pn) * 128 + lane * 4);
            mma_bf16(c[2*pn][0], c[2*pn][1], c[2*pn][2], c[2*pn][3],
                     a0, a1, a2, a3, bb.x, bb.y);
            mma_bf16(c[2*pn+1][0], c[2*pn+1][1], c[2*pn+1][2], c[2*pn+1][3],
                     a0, a1, a2, a3, bb.z, bb.w);
        }
    }

    // ---- boundary 1 (REGISTER-RESIDENT): h1 A-fragments from C-fragments.
    // A-frag k-tile kt: a0 = c[2kt][0..1], a1 = c[2kt][2..3],
    //                   a2 = c[2kt+1][0..1], a3 = c[2kt+1][2..3] (gelu+pack).
    uint ha[4][4];
#pragma unroll
    for (int kt = 0; kt < 4; ++kt) {
        ha[kt][0] = bf2(gelu_fast(c[2*kt][0]),   gelu_fast(c[2*kt][1]));
        ha[kt][1] = bf2(gelu_fast(c[2*kt][2]),   gelu_fast(c[2*kt][3]));
        ha[kt][2] = bf2(gelu_fast(c[2*kt+1][0]), gelu_fast(c[2*kt+1][1]));
        ha[kt][3] = bf2(gelu_fast(c[2*kt+1][2]), gelu_fast(c[2*kt+1][3]));
    }

    // ---- GEMM2: (16x64) @ W2(64x64) + bk2 (4 k16 tiles; A in registers)
#pragma unroll
    for (int nt = 0; nt < 8; ++nt) {
        float b0 = cbk2[nt * 8 + 2 * t0], b1 = cbk2[nt * 8 + 2 * t0 + 1];
        c[nt][0] = b0; c[nt][1] = b1; c[nt][2] = b0; c[nt][3] = b1;
    }
#pragma unroll
    for (int kt = 0; kt < 4; ++kt) {
#pragma unroll
        for (int pn = 0; pn < 4; ++pn) {
            uint4 bb = *(const uint4*)(gwf + W2F_OFF + (kt * 4 + pn) * 128 + lane * 4);
            mma_bf16(c[2*pn][0], c[2*pn][1], c[2*pn][2], c[2*pn][3],
                     ha[kt][0], ha[kt][1], ha[kt][2], ha[kt][3], bb.x, bb.y);
            mma_bf16(c[2*pn+1][0], c[2*pn+1][1], c[2*pn+1][2], c[2*pn+1][3],
                     ha[kt][0], ha[kt][1], ha[kt][2], ha[kt][3], bb.z, bb.w);
        }
    }

    // ---- boundary 2 (REGISTER-RESIDENT): h2 A-fragments from C-fragments.
#pragma unroll
    for (int kt = 0; kt < 4; ++kt) {
        ha[kt][0] = bf2(gelu_fast(c[2*kt][0]),   gelu_fast(c[2*kt][1]));
        ha[kt][1] = bf2(gelu_fast(c[2*kt][2]),   gelu_fast(c[2*kt][3]));
        ha[kt][2] = bf2(gelu_fast(c[2*kt+1][0]), gelu_fast(c[2*kt+1][1]));
        ha[kt][3] = bf2(gelu_fast(c[2*kt+1][2]), gelu_fast(c[2*kt+1][3]));
    }

    // ---- GEMM3: (16x64) @ W3(64x32) + bk3 (4 k16 tiles; A in registers)
    float c3[4][4];
#pragma unroll
    for (int nt = 0; nt < 4; ++nt) {
        float b0 = cbk3[nt * 8 + 2 * t0], b1 = cbk3[nt * 8 + 2 * t0 + 1];
        c3[nt][0] = b0; c3[nt][1] = b1; c3[nt][2] = b0; c3[nt][3] = b1;
    }
#pragma unroll
    for (int kt = 0; kt < 4; ++kt) {
#pragma unroll
        for (int pn = 0; pn < 2; ++pn) {
            uint4 bb = *(const uint4*)(gwf + W3F_OFF + (kt * 2 + pn) * 128 + lane * 4);
            mma_bf16(c3[2*pn][0], c3[2*pn][1], c3[2*pn][2], c3[2*pn][3],
                     ha[kt][0], ha[kt][1], ha[kt][2], ha[kt][3], bb.x, bb.y);
            mma_bf16(c3[2*pn+1][0], c3[2*pn+1][1], c3[2*pn+1][2], c3[2*pn+1][3],
                     ha[kt][0], ha[kt][1], ha[kt][2], ha[kt][3], bb.z, bb.w);
        }
    }

    // ---- Mean over K = sum over 16 rows of the 16x32 tile
    float s[8];
#pragma unroll
    for (int nt = 0; nt < 4; ++nt) {
        s[2*nt + 0] = c3[nt][0] + c3[nt][2];
        s[2*nt + 1] = c3[nt][1] + c3[nt][3];
    }
#pragma unroll
    for (int off = 4; off <= 16; off <<= 1) {
#pragma unroll
        for (int i = 0; i < 8; ++i)
            s[i] += __shfl_xor_sync(0xffffffffu, s[i], off);
    }

    // ---- residual + LayerNorm epilogue (valid work in gid==0 lanes)
    float o[8];
    if (gid == 0) {
#pragma unroll
        for (int nt = 0; nt < 4; ++nt) {
            float2 xv = *(const float2*)(g_x + node * OUT_DIM + nt * 8 + 2 * t0);
            o[2*nt + 0] = fmaf(s[2*nt + 0], 0.0625f, xv.x);
            o[2*nt + 1] = fmaf(s[2*nt + 1], 0.0625f, xv.y);
        }
    } else {
#pragma unroll
        for (int i = 0; i < 8; ++i) o[i] = 0.0f;
    }
    float part = 0.0f;
#pragma unroll
    for (int i = 0; i < 8; ++i) part += o[i];
    part += __shfl_xor_sync(0xffffffffu, part, 1);
    part += __shfl_xor_sync(0xffffffffu, part, 2);
    float mu = part * (1.0f / OUT_DIM);
    float vp = 0.0f;
#pragma unroll
    for (int i = 0; i < 8; ++i) { float d = o[i] - mu; vp = fmaf(d, d, vp); }
    vp += __shfl_xor_sync(0xffffffffu, vp, 1);
    vp += __shfl_xor_sync(0xffffffffu, vp, 2);
    if (gid == 0) {
        float rs = rsqrtf(vp * (1.0f / OUT_DIM) + 1e-5f);
#pragma unroll
        for (int nt = 0; nt < 4; ++nt) {
            int col = nt * 8 + 2 * t0;
            float2 y;
            y.x = fmaf((o[2*nt + 0] - mu) * rs, cG[col + 0], cBt[col + 0]);
            y.y = fmaf((o[2*nt + 1] - mu) * rs, cG[col + 1], cBt[col + 1]);
            *(float2*)(out + node * OUT_DIM + col) = y;
        }
    }
}

// ---------------------------------------------------------------------------
extern "C" void kernel_launch(void* const* d_in, const int* in_sizes, int n_in,
                              void* d_out, int out_size) {
    const float* inp   = (const float*)d_in[0];
    const float* igrid = (const float*)d_in[1];
    const float* ogrid = (const float*)d_in[2];
    const int*   nidx  = (const int*)  d_in[3];
    const float* Wp1   = (const float*)d_in[4];
    const float* bp1   = (const float*)d_in[5];
    const float* Wp2   = (const float*)d_in[6];
    const float* bp2   = (const float*)d_in[7];
    const float* Wk1   = (const float*)d_in[8];
    const float* bk1   = (const float*)d_in[9];
    const float* Wk2   = (const float*)d_in[10];
    const float* bk2   = (const float*)d_in[11];
    const float* Wk3   = (const float*)d_in[12];
    const float* bk3   = (const float*)d_in[13];
    const float* ln_g  = (const float*)d_in[14];
    const float* ln_b  = (const float*)d_in[15];
    float* out = (float*)d_out;

    cudaMemcpyToSymbolAsync(cbk1, bk1, KH * sizeof(float), 0, cudaMemcpyDeviceToDevice);
    cudaMemcpyToSymbolAsync(cbk2, bk2, KH * sizeof(float), 0, cudaMemcpyDeviceToDevice);
    cudaMemcpyToSymbolAsync(cbk3, bk3, OUT_DIM * sizeof(float), 0, cudaMemcpyDeviceToDevice);
    cudaMemcpyToSymbolAsync(cG,   ln_g, OUT_DIM * sizeof(float), 0, cudaMemcpyDeviceToDevice);
    cudaMemcpyToSymbolAsync(cBt,  ln_b, OUT_DIM * sizeof(float), 0, cudaMemcpyDeviceToDevice);
    cudaMemcpyToSymbolAsync(cWp1, Wp1, IN_DIM * HID * sizeof(float), 0, cudaMemcpyDeviceToDevice);
    cudaMemcpyToSymbolAsync(cWp2, Wp2, HID * OUT_DIM * sizeof(float), 0, cudaMemcpyDeviceToDevice);
    cudaMemcpyToSymbolAsync(cbp1, bp1, HID * sizeof(float), 0, cudaMemcpyDeviceToDevice);
    cudaMemcpyToSymbolAsync(cbp2, bp2, OUT_DIM * sizeof(float), 0, cudaMemcpyDeviceToDevice);

    pack_weights<<<32, 256>>>(Wk1, Wk2, Wk3);
    pointwise_kernel<<<(BB * NN) / 256, 256>>>(inp);
    edge_kernel<<<(BB * NN) / NPB, 128, EDGE_SMEM_BYTES>>>(igrid, ogrid, nidx, out);
}